// round 13
// baseline (speedup 1.0000x reference)
#include <cuda_runtime.h>

// out[i,j,k] = C[i,j,k] * x[i,j]
// B=4096, INPUT_SIZE=512, EMBED_DIM=64 -> n = 2^27 floats, n4 = 2^25 float4
//
// v13: persistent single-wave kernel. Grid = 296 blocks (2 per SM, 148 SMs)
// of 512 threads; each block grid-strides over contiguous 4096-float4 (64KB)
// tiles. Identical per-tile memory pattern to the R6 winner (8x LDG.128
// front-batch, ldcs/stcs), but zero wave transitions / block churn.

#define THREADS 512
#define UNROLL  8
#define PERSIST_BLOCKS (148 * 2)

__global__ __launch_bounds__(THREADS)
void bcast_mul_persist(const float* __restrict__ x,
                       const float4* __restrict__ C4,
                       float4* __restrict__ out4,
                       unsigned n_tiles) {
    const unsigned tile_elems = THREADS * UNROLL;       // 4096 float4

    for (unsigned t = blockIdx.x; t < n_tiles; t += gridDim.x) {
        const unsigned base = t * tile_elems + threadIdx.x;

        float4 c[UNROLL];
        float  s[UNROLL];
#pragma unroll
        for (int j = 0; j < UNROLL; j++) {
            unsigned i = base + j * THREADS;
            c[j] = __ldcs(&C4[i]);
            s[j] = __ldg(&x[i >> 4]);      // 16 float4-groups per x scalar
        }
#pragma unroll
        for (int j = 0; j < UNROLL; j++) {
            unsigned i = base + j * THREADS;
            float4 o;
            o.x = c[j].x * s[j];
            o.y = c[j].y * s[j];
            o.z = c[j].z * s[j];
            o.w = c[j].w * s[j];
            __stcs(&out4[i], o);
        }
    }
}

__global__ void bcast_mul_generic(const float* __restrict__ x,
                                  const float4* __restrict__ C4,
                                  float4* __restrict__ out4,
                                  unsigned n4) {
    unsigned i = blockIdx.x * blockDim.x + threadIdx.x;
    if (i < n4) {
        float s = __ldg(&x[i >> 4]);
        float4 c = __ldcs(&C4[i]);
        float4 o;
        o.x = c.x * s; o.y = c.y * s; o.z = c.z * s; o.w = c.w * s;
        __stcs(&out4[i], o);
    }
}

extern "C" void kernel_launch(void* const* d_in, const int* in_sizes, int n_in,
                              void* d_out, int out_size) {
    const float* x;
    const float* C;
    if (in_sizes[0] < in_sizes[1]) {
        x = (const float*)d_in[0];
        C = (const float*)d_in[1];
    } else {
        x = (const float*)d_in[1];
        C = (const float*)d_in[0];
    }

    unsigned n4 = (unsigned)((long long)out_size >> 2);   // 33,554,432
    const unsigned per_block = THREADS * UNROLL;          // 4096

    if (n4 % per_block == 0) {
        unsigned n_tiles = n4 / per_block;                // 8192
        bcast_mul_persist<<<PERSIST_BLOCKS, THREADS>>>(
            x, (const float4*)C, (float4*)d_out, n_tiles);
    } else {
        bcast_mul_generic<<<(n4 + 255) / 256, 256>>>(
            x, (const float4*)C, (float4*)d_out, n4);
    }
}

// round 14
// speedup vs baseline: 1.0797x; 1.0797x over previous
#include <cuda_runtime.h>

// out[i,j,k] = C[i,j,k] * x[i,j]
// B=4096, INPUT_SIZE=512, EMBED_DIM=64 -> n = 2^27 floats, n4 = 2^25 float4
//
// FINAL kernel — best measured config (157.1us wall; repro 157.9/157.7/158.0),
// 6.75 TB/s = ~85% of HBM spec on provably-minimal traffic (1.032 GB).
//
//  - 512 threads x 8 unroll, block-contiguous 4096-float4 (64KB r + 64KB w) tiles
//  - one short-lived block per tile (HW scheduler pipelines blocks better than
//    a persistent loop: persistence cost -9% BW, tested R13)
//  - exact-division fast kernel, zero predication; generic fallback for safety
//  - __ldcs on C (read-once), __stcs on out (beats __stwt, R7),
//    __ldg on x (L2-resident, 64x reuse)
//
// Search exhausted R1-R13: vector width {128b,256b}, MLP {1,4,8,16},
// threads {256,512}, tiling {grid-stride, block-contiguous, persistent},
// store {cs,wt}, ld/st phasing {batched, pipelined}, occupancy {32-79%}.
// Binding resource: achieved HBM bandwidth on a 1:1 read/write stream
// (bus turnaround + refresh ceiling). Nothing SM-side moves it.

#define THREADS 512
#define UNROLL  8

__global__ __launch_bounds__(THREADS)
void bcast_mul_exact(const float* __restrict__ x,
                     const float4* __restrict__ C4,
                     float4* __restrict__ out4) {
    const unsigned base = blockIdx.x * (THREADS * UNROLL) + threadIdx.x;

    float4 c[UNROLL];
    float  s[UNROLL];
#pragma unroll
    for (int j = 0; j < UNROLL; j++) {
        unsigned i = base + j * THREADS;
        c[j] = __ldcs(&C4[i]);
        s[j] = __ldg(&x[i >> 4]);          // 16 float4-groups per x scalar
    }
#pragma unroll
    for (int j = 0; j < UNROLL; j++) {
        unsigned i = base + j * THREADS;
        float4 o;
        o.x = c[j].x * s[j];
        o.y = c[j].y * s[j];
        o.z = c[j].z * s[j];
        o.w = c[j].w * s[j];
        __stcs(&out4[i], o);
    }
}

__global__ void bcast_mul_generic(const float* __restrict__ x,
                                  const float4* __restrict__ C4,
                                  float4* __restrict__ out4,
                                  unsigned n4) {
    unsigned i = blockIdx.x * blockDim.x + threadIdx.x;
    if (i < n4) {
        float s = __ldg(&x[i >> 4]);
        float4 c = __ldcs(&C4[i]);
        float4 o;
        o.x = c.x * s; o.y = c.y * s; o.z = c.z * s; o.w = c.w * s;
        __stcs(&out4[i], o);
    }
}

extern "C" void kernel_launch(void* const* d_in, const int* in_sizes, int n_in,
                              void* d_out, int out_size) {
    const float* x;
    const float* C;
    if (in_sizes[0] < in_sizes[1]) {
        x = (const float*)d_in[0];
        C = (const float*)d_in[1];
    } else {
        x = (const float*)d_in[1];
        C = (const float*)d_in[0];
    }

    unsigned n4 = (unsigned)((long long)out_size >> 2);   // 33,554,432
    const unsigned per_block = THREADS * UNROLL;          // 4096

    if (n4 % per_block == 0) {
        bcast_mul_exact<<<n4 / per_block, THREADS>>>(
            x, (const float4*)C, (float4*)d_out);
    } else {
        bcast_mul_generic<<<(n4 + 255) / 256, 256>>>(
            x, (const float4*)C, (float4*)d_out, n4);
    }
}

// round 15
// speedup vs baseline: 1.0827x; 1.0029x over previous
#include <cuda_runtime.h>

// out[i,j,k] = C[i,j,k] * x[i,j]
// B=4096, INPUT_SIZE=512, EMBED_DIM=64 -> n = 2^27 floats, n4 = 2^25 float4
//
// v15: final grid point on the geometry axis — 1024 threads x 4 unroll
// (same 64KB block tile as the 512x8 winner; 8192 blocks). Everything else
// identical to the proven config: front-batched LDG.128, __ldcs/__stcs on
// the streams, __ldg on L2-resident x, zero predication on exact division.

#define THREADS 1024
#define UNROLL  4

__global__ __launch_bounds__(THREADS)
void bcast_mul_exact(const float* __restrict__ x,
                     const float4* __restrict__ C4,
                     float4* __restrict__ out4) {
    const unsigned base = blockIdx.x * (THREADS * UNROLL) + threadIdx.x;

    float4 c[UNROLL];
    float  s[UNROLL];
#pragma unroll
    for (int j = 0; j < UNROLL; j++) {
        unsigned i = base + j * THREADS;
        c[j] = __ldcs(&C4[i]);
        s[j] = __ldg(&x[i >> 4]);          // 16 float4-groups per x scalar
    }
#pragma unroll
    for (int j = 0; j < UNROLL; j++) {
        unsigned i = base + j * THREADS;
        float4 o;
        o.x = c[j].x * s[j];
        o.y = c[j].y * s[j];
        o.z = c[j].z * s[j];
        o.w = c[j].w * s[j];
        __stcs(&out4[i], o);
    }
}

__global__ void bcast_mul_generic(const float* __restrict__ x,
                                  const float4* __restrict__ C4,
                                  float4* __restrict__ out4,
                                  unsigned n4) {
    unsigned i = blockIdx.x * blockDim.x + threadIdx.x;
    if (i < n4) {
        float s = __ldg(&x[i >> 4]);
        float4 c = __ldcs(&C4[i]);
        float4 o;
        o.x = c.x * s; o.y = c.y * s; o.z = c.z * s; o.w = c.w * s;
        __stcs(&out4[i], o);
    }
}

extern "C" void kernel_launch(void* const* d_in, const int* in_sizes, int n_in,
                              void* d_out, int out_size) {
    const float* x;
    const float* C;
    if (in_sizes[0] < in_sizes[1]) {
        x = (const float*)d_in[0];
        C = (const float*)d_in[1];
    } else {
        x = (const float*)d_in[1];
        C = (const float*)d_in[0];
    }

    unsigned n4 = (unsigned)((long long)out_size >> 2);   // 33,554,432
    const unsigned per_block = THREADS * UNROLL;          // 4096

    if (n4 % per_block == 0) {
        bcast_mul_exact<<<n4 / per_block, THREADS>>>(
            x, (const float4*)C, (float4*)d_out);
    } else {
        bcast_mul_generic<<<(n4 + 255) / 256, 256>>>(
            x, (const float4*)C, (float4*)d_out, n4);
    }
}